// round 5
// baseline (speedup 1.0000x reference)
#include <cuda_runtime.h>
#include <cstdint>

#define N_NODES 50000
#define NT      100000          // combined node space (graph0 + graph1)
#define D 128
#define NE 800000
#define NET (2 * NE)            // combined edges
#define BM 128
#define SCAN_NBLK ((NT + 1023) / 1024)   // 98
#define GEMM_SMEM (2 * 128 * 128 * 4)    // As 64KB + Ws 64KB

// -------- device scratch --------
__device__ float g_h[(size_t)NT * D];
__device__ float g_agg[(size_t)NT * D];
__device__ float g_buf[(size_t)NT * D];
__device__ float g_dis[NT];
__device__ int   g_cnt[NT];
__device__ int   g_off[NT];
__device__ int   g_cur[NT];
__device__ int   g_csrc[NET];
__device__ float g_cw[NET];
__device__ int   g_bsum[128];

// packed f32x2 helpers (baseline sm_100+ PTX, not 'a'-gated)
#define PACK_AA(out, af) \
    asm("mov.b64 %0, {%1, %1};" : "=l"(out) : "r"(af))
#define FMA2(d, a, b, c) \
    asm("fma.rn.f32x2 %0, %1, %2, %3;" : "=l"(d) : "l"(a), "l"(b), "l"(c))
#define UNPACK2(lo, hi, in) \
    asm("mov.b64 {%0, %1}, %2;" : "=f"(lo), "=f"(hi) : "l"(in))

// -------- CSR build over combined edge set --------
__global__ void zero_kernel() {
    int i = blockIdx.x * blockDim.x + threadIdx.x;
    if (i < NT) { g_cnt[i] = 0; g_cur[i] = 0; }
}
__global__ void count_kernel(const int* __restrict__ e0, const int* __restrict__ e1) {
    int e = blockIdx.x * blockDim.x + threadIdx.x;
    if (e >= NET) return;
    int d = (e < NE) ? __ldg(e0 + NE + e) : (__ldg(e1 + NE + (e - NE)) + N_NODES);
    atomicAdd(&g_cnt[d], 1);
}
__global__ void dis_kernel() {
    int i = blockIdx.x * blockDim.x + threadIdx.x;
    if (i < NT) g_dis[i] = rsqrtf((float)g_cnt[i] + 1.0f);
}
__global__ void scan1_kernel() {
    __shared__ int sh[1024];
    int i = blockIdx.x * 1024 + threadIdx.x;
    int v = (i < NT) ? g_cnt[i] : 0;
    sh[threadIdx.x] = v;
    __syncthreads();
#pragma unroll
    for (int ofs = 1; ofs < 1024; ofs <<= 1) {
        int t = (threadIdx.x >= ofs) ? sh[threadIdx.x - ofs] : 0;
        __syncthreads();
        sh[threadIdx.x] += t;
        __syncthreads();
    }
    if (i < NT) g_off[i] = sh[threadIdx.x] - v;
    if (threadIdx.x == 1023) g_bsum[blockIdx.x] = sh[1023];
}
__global__ void scan2_kernel() {
    __shared__ int sh[128];
    int v = (threadIdx.x < SCAN_NBLK) ? g_bsum[threadIdx.x] : 0;
    sh[threadIdx.x] = v;
    __syncthreads();
#pragma unroll
    for (int ofs = 1; ofs < 128; ofs <<= 1) {
        int t = (threadIdx.x >= ofs) ? sh[threadIdx.x - ofs] : 0;
        __syncthreads();
        sh[threadIdx.x] += t;
        __syncthreads();
    }
    if (threadIdx.x < SCAN_NBLK) g_bsum[threadIdx.x] = sh[threadIdx.x] - v;
}
__global__ void scan3_kernel() {
    int i = blockIdx.x * blockDim.x + threadIdx.x;
    if (i < NT) g_off[i] += g_bsum[i >> 10];
}
__global__ void fill_kernel(const int* __restrict__ e0, const int* __restrict__ e1) {
    int e = blockIdx.x * blockDim.x + threadIdx.x;
    if (e >= NET) return;
    int s, d;
    if (e < NE) { s = __ldg(e0 + e);          d = __ldg(e0 + NE + e); }
    else        { s = __ldg(e1 + (e - NE)) + N_NODES;
                  d = __ldg(e1 + NE + (e - NE)) + N_NODES; }
    int p = g_off[d] + atomicAdd(&g_cur[d], 1);
    g_csrc[p] = s;
    g_cw[p]   = g_dis[s] * g_dis[d];
}

// -------- GEMM: C[M,128] = A[M,128] @ W[128,128] (+ epilogue), f32x2 --------
// Rows < N_NODES read from A0, rows >= N_NODES read from A1 (row - N_NODES).
// mode 0: C = h, C2 = h*dis[m]^2 + bias
// mode 1: C = relu(h + bias)
// mode 2: C = h + bias
__global__ __launch_bounds__(512, 1)
void gemm_kernel(const float* __restrict__ A0, const float* __restrict__ A1,
                 const float* __restrict__ W, const float* __restrict__ bias,
                 float* __restrict__ C, float* __restrict__ C2,
                 int M, int mode)
{
    extern __shared__ float smem[];
    float* As = smem;               // [128][128] row-major
    float* Ws = smem + 128 * 128;   // [k][n] row-major

    const int tid = threadIdx.x;
    const int m0  = blockIdx.x * BM;

    const float4 z4 = make_float4(0.f, 0.f, 0.f, 0.f);
#pragma unroll
    for (int i = 0; i < 8; i++) {
        int f  = i * 512 + tid;       // float4 index
        int m  = f >> 5;
        int k4 = f & 31;
        int gm = m0 + m;
        float4 v = z4;
        if (gm < M) {
            const float* base = (gm < N_NODES) ? (A0 + (size_t)gm * D)
                                               : (A1 + (size_t)(gm - N_NODES) * D);
            v = __ldg((const float4*)base + k4);
        }
        *(float4*)(As + m * D + k4 * 4) = v;
    }
#pragma unroll
    for (int i = 0; i < 8; i++) {
        int f = i * 512 + tid;
        ((float4*)Ws)[f] = __ldg((const float4*)W + f);
    }
    __syncthreads();

    const int ty  = tid >> 4;     // 0..31
    const int tx  = tid & 15;     // 0..15
    const int row = ty * 4;
    const int col = tx * 8;

    unsigned long long acc[4][4];
#pragma unroll
    for (int i = 0; i < 4; i++)
#pragma unroll
        for (int j = 0; j < 4; j++) acc[i][j] = 0ull;

#pragma unroll 8
    for (int k = 0; k < D; k++) {
        ulonglong2 b01 = *(const ulonglong2*)(Ws + k * D + col);
        ulonglong2 b23 = *(const ulonglong2*)(Ws + k * D + col + 4);
        unsigned long long b[4] = {b01.x, b01.y, b23.x, b23.y};
#pragma unroll
        for (int i = 0; i < 4; i++) {
            unsigned long long aa;
            PACK_AA(aa, __float_as_uint(As[(row + i) * D + k]));
#pragma unroll
            for (int j = 0; j < 4; j++) FMA2(acc[i][j], aa, b[j], acc[i][j]);
        }
    }

    float bb[8];
    {
        float4 t0 = __ldg((const float4*)(bias + col));
        float4 t1 = __ldg((const float4*)(bias + col + 4));
        bb[0]=t0.x; bb[1]=t0.y; bb[2]=t0.z; bb[3]=t0.w;
        bb[4]=t1.x; bb[5]=t1.y; bb[6]=t1.z; bb[7]=t1.w;
    }
#pragma unroll
    for (int i = 0; i < 4; i++) {
        int m = m0 + row + i;
        if (m >= M) break;
        float v[8];
#pragma unroll
        for (int j = 0; j < 4; j++) UNPACK2(v[2*j], v[2*j+1], acc[i][j]);

        if (mode == 0) {
            float dd = g_dis[m];
            float d2 = dd * dd;
            float* cp  = C  + (size_t)m * D + col;
            float* cp2 = C2 + (size_t)m * D + col;
            *(float4*)cp       = make_float4(v[0], v[1], v[2], v[3]);
            *(float4*)(cp + 4) = make_float4(v[4], v[5], v[6], v[7]);
            *(float4*)cp2       = make_float4(fmaf(v[0], d2, bb[0]), fmaf(v[1], d2, bb[1]),
                                              fmaf(v[2], d2, bb[2]), fmaf(v[3], d2, bb[3]));
            *(float4*)(cp2 + 4) = make_float4(fmaf(v[4], d2, bb[4]), fmaf(v[5], d2, bb[5]),
                                              fmaf(v[6], d2, bb[6]), fmaf(v[7], d2, bb[7]));
        } else {
            float o[8];
#pragma unroll
            for (int j = 0; j < 8; j++) {
                float t = v[j] + bb[j];
                o[j] = (mode == 1) ? fmaxf(t, 0.0f) : t;
            }
            float* cp = C + (size_t)m * D + col;
            *(float4*)cp       = make_float4(o[0], o[1], o[2], o[3]);
            *(float4*)(cp + 4) = make_float4(o[4], o[5], o[6], o[7]);
        }
    }
}

// -------- gather: out[v] = relu( init[v] + sum_{e: dst=v} w_e * h[src_e] ) --------
__global__ void gather_kernel(float* __restrict__ out) {
    int node = blockIdx.x * 8 + (threadIdx.x >> 5);
    int lane = threadIdx.x & 31;
    if (node >= NT) return;
    int beg = g_off[node];
    int cnt = g_cnt[node];
    float4 a0 = *((const float4*)(g_agg + (size_t)node * D) + lane);
    float4 a1 = make_float4(0.f, 0.f, 0.f, 0.f);
    float4 a2 = make_float4(0.f, 0.f, 0.f, 0.f);
    float4 a3 = make_float4(0.f, 0.f, 0.f, 0.f);

    int j = 0;
    for (; j + 4 <= cnt; j += 4) {
        int   s0 = __ldg(&g_csrc[beg + j]);
        int   s1 = __ldg(&g_csrc[beg + j + 1]);
        int   s2 = __ldg(&g_csrc[beg + j + 2]);
        int   s3 = __ldg(&g_csrc[beg + j + 3]);
        float w0 = __ldg(&g_cw[beg + j]);
        float w1 = __ldg(&g_cw[beg + j + 1]);
        float w2 = __ldg(&g_cw[beg + j + 2]);
        float w3 = __ldg(&g_cw[beg + j + 3]);
        float4 v0 = __ldg((const float4*)(g_h + (size_t)s0 * D) + lane);
        float4 v1 = __ldg((const float4*)(g_h + (size_t)s1 * D) + lane);
        float4 v2 = __ldg((const float4*)(g_h + (size_t)s2 * D) + lane);
        float4 v3 = __ldg((const float4*)(g_h + (size_t)s3 * D) + lane);
        a0.x = fmaf(w0, v0.x, a0.x); a0.y = fmaf(w0, v0.y, a0.y);
        a0.z = fmaf(w0, v0.z, a0.z); a0.w = fmaf(w0, v0.w, a0.w);
        a1.x = fmaf(w1, v1.x, a1.x); a1.y = fmaf(w1, v1.y, a1.y);
        a1.z = fmaf(w1, v1.z, a1.z); a1.w = fmaf(w1, v1.w, a1.w);
        a2.x = fmaf(w2, v2.x, a2.x); a2.y = fmaf(w2, v2.y, a2.y);
        a2.z = fmaf(w2, v2.z, a2.z); a2.w = fmaf(w2, v2.w, a2.w);
        a3.x = fmaf(w3, v3.x, a3.x); a3.y = fmaf(w3, v3.y, a3.y);
        a3.z = fmaf(w3, v3.z, a3.z); a3.w = fmaf(w3, v3.w, a3.w);
    }
    for (; j < cnt; j++) {
        int   s = __ldg(&g_csrc[beg + j]);
        float w = __ldg(&g_cw[beg + j]);
        float4 v = __ldg((const float4*)(g_h + (size_t)s * D) + lane);
        a0.x = fmaf(w, v.x, a0.x); a0.y = fmaf(w, v.y, a0.y);
        a0.z = fmaf(w, v.z, a0.z); a0.w = fmaf(w, v.w, a0.w);
    }
    a0.x = fmaxf(a0.x + a1.x + a2.x + a3.x, 0.0f);
    a0.y = fmaxf(a0.y + a1.y + a2.y + a3.y, 0.0f);
    a0.z = fmaxf(a0.z + a1.z + a2.z + a3.z, 0.0f);
    a0.w = fmaxf(a0.w + a1.w + a2.w + a3.w, 0.0f);
    *((float4*)(out + (size_t)node * D) + lane) = a0;
}

extern "C" void kernel_launch(void* const* d_in, const int* in_sizes, int n_in,
                              void* d_out, int out_size)
{
    const float* x    = (const float*)d_in[0];
    const int*   ei   = (const int*)  d_in[1];
    const float* xa   = (const float*)d_in[2];
    const int*   eia  = (const int*)  d_in[3];
    const float* W_in = (const float*)d_in[4];
    const float* b_in = (const float*)d_in[5];
    const float* W_h  = (const float*)d_in[6];
    const float* b_h  = (const float*)d_in[7];
    const float* W_out= (const float*)d_in[8];
    const float* b_out= (const float*)d_in[9];
    const float* Wf1  = (const float*)d_in[10];
    const float* bf1  = (const float*)d_in[11];
    const float* Wf2  = (const float*)d_in[12];
    const float* bf2  = (const float*)d_in[13];
    float* out = (float*)d_out;

    cudaFuncSetAttribute(gemm_kernel,
        cudaFuncAttributeMaxDynamicSharedMemorySize, GEMM_SMEM);

    float *hp, *aggp, *bufp;
    cudaGetSymbolAddress((void**)&hp,   g_h);
    cudaGetSymbolAddress((void**)&aggp, g_agg);
    cudaGetSymbolAddress((void**)&bufp, g_buf);

    const int gemm_blocks   = (NT + BM - 1) / BM;       // 782
    const int node_blocks   = (NT + 255) / 256;         // 391
    const int edge_blocks   = (NET + 255) / 256;        // 6250
    const int gather_blocks = (NT + 7) / 8;             // 12500

    // combined CSR build (once for both graphs)
    zero_kernel<<<node_blocks, 256>>>();
    count_kernel<<<edge_blocks, 256>>>(ei, eia);
    dis_kernel<<<node_blocks, 256>>>();
    scan1_kernel<<<SCAN_NBLK, 1024>>>();
    scan2_kernel<<<1, 128>>>();
    scan3_kernel<<<node_blocks, 256>>>();
    fill_kernel<<<edge_blocks, 256>>>(ei, eia);

    const float* Wl[3] = {W_in, W_h, W_out};
    const float* bl[3] = {b_in, b_h, b_out};

    // 3 GCN layers over the combined 100K-node batch
    const float* in0 = x;
    const float* in1 = xa;
    for (int l = 0; l < 3; l++) {
        gemm_kernel<<<gemm_blocks, 512, GEMM_SMEM>>>(
            in0, in1, Wl[l], bl[l], hp, aggp, NT, 0);
        gather_kernel<<<gather_blocks, 256>>>(bufp);
        in0 = bufp;
        in1 = bufp + (size_t)N_NODES * D;
    }

    // MLP head; final GEMM writes straight into d_out (out | out_aug layout)
    gemm_kernel<<<gemm_blocks, 512, GEMM_SMEM>>>(
        bufp, bufp + (size_t)N_NODES * D, Wf1, bf1, hp, nullptr, NT, 1);
    gemm_kernel<<<gemm_blocks, 512, GEMM_SMEM>>>(
        hp, hp + (size_t)N_NODES * D, Wf2, bf2, out, nullptr, NT, 2);
}

// round 6
// speedup vs baseline: 1.2540x; 1.2540x over previous
#include <cuda_runtime.h>
#include <cstdint>

#define N_NODES 50000
#define NT      100000          // combined node space (graph0 + graph1)
#define D 128
#define NE 800000
#define NET (2 * NE)
#define BM 128
#define SCAN_NBLK ((NT + 1023) / 1024)   // 98
#define GEMM_SMEM (2 * 128 * 128 * 4)    // As 64KB + Ws 64KB

// -------- device scratch --------
__device__ float g_h[(size_t)NT * D];
__device__ float g_agg[(size_t)NT * D];
__device__ float g_buf[(size_t)NT * D];
__device__ float g_dis[NT];
__device__ int   g_cnt[NT];
__device__ int   g_off[NT];
__device__ int   g_cur[NT];
__device__ int   g_csrc[NET];
__device__ float g_cw[NET];
__device__ int   g_bsum[128];

// packed f32x2 helpers (baseline sm_100+ PTX, not 'a'-gated)
#define PACK_AA(out, af) \
    asm("mov.b64 %0, {%1, %1};" : "=l"(out) : "r"(af))
#define FMA2(d, a, b, c) \
    asm("fma.rn.f32x2 %0, %1, %2, %3;" : "=l"(d) : "l"(a), "l"(b), "l"(c))
#define UNPACK2(lo, hi, in) \
    asm("mov.b64 {%0, %1}, %2;" : "=f"(lo), "=f"(hi) : "l"(in))

// -------- CSR build over combined edge set --------
__global__ void zero_kernel() {
    int i = blockIdx.x * blockDim.x + threadIdx.x;
    if (i < NT) { g_cnt[i] = 0; g_cur[i] = 0; }
}
__global__ void count_kernel(const int* __restrict__ e0, const int* __restrict__ e1) {
    int e = blockIdx.x * blockDim.x + threadIdx.x;
    if (e >= NET) return;
    int d = (e < NE) ? __ldg(e0 + NE + e) : (__ldg(e1 + NE + (e - NE)) + N_NODES);
    atomicAdd(&g_cnt[d], 1);
}
__global__ void dis_kernel() {
    int i = blockIdx.x * blockDim.x + threadIdx.x;
    if (i < NT) g_dis[i] = rsqrtf((float)g_cnt[i] + 1.0f);
}
__global__ void scan1_kernel() {
    __shared__ int sh[1024];
    int i = blockIdx.x * 1024 + threadIdx.x;
    int v = (i < NT) ? g_cnt[i] : 0;
    sh[threadIdx.x] = v;
    __syncthreads();
#pragma unroll
    for (int ofs = 1; ofs < 1024; ofs <<= 1) {
        int t = (threadIdx.x >= ofs) ? sh[threadIdx.x - ofs] : 0;
        __syncthreads();
        sh[threadIdx.x] += t;
        __syncthreads();
    }
    if (i < NT) g_off[i] = sh[threadIdx.x] - v;
    if (threadIdx.x == 1023) g_bsum[blockIdx.x] = sh[1023];
}
__global__ void scan2_kernel() {
    __shared__ int sh[128];
    int v = (threadIdx.x < SCAN_NBLK) ? g_bsum[threadIdx.x] : 0;
    sh[threadIdx.x] = v;
    __syncthreads();
#pragma unroll
    for (int ofs = 1; ofs < 128; ofs <<= 1) {
        int t = (threadIdx.x >= ofs) ? sh[threadIdx.x - ofs] : 0;
        __syncthreads();
        sh[threadIdx.x] += t;
        __syncthreads();
    }
    if (threadIdx.x < SCAN_NBLK) g_bsum[threadIdx.x] = sh[threadIdx.x] - v;
}
__global__ void scan3_kernel() {
    int i = blockIdx.x * blockDim.x + threadIdx.x;
    if (i < NT) g_off[i] += g_bsum[i >> 10];
}
__global__ void fill_kernel(const int* __restrict__ e0, const int* __restrict__ e1) {
    int e = blockIdx.x * blockDim.x + threadIdx.x;
    if (e >= NET) return;
    int s, d;
    if (e < NE) { s = __ldg(e0 + e);          d = __ldg(e0 + NE + e); }
    else        { s = __ldg(e1 + (e - NE)) + N_NODES;
                  d = __ldg(e1 + NE + (e - NE)) + N_NODES; }
    int p = g_off[d] + atomicAdd(&g_cur[d], 1);
    g_csrc[p] = s;
    g_cw[p]   = g_dis[s] * g_dis[d];
}

// -------- GEMM: C[M,128] = A[M,128] @ W[128,128] (+ epilogue), f32x2 --------
// R4-proven shape: 256 threads, 8 rows x 8 cols per thread.
// Rows < N_NODES read from A0, rows >= N_NODES from A1 (row - N_NODES).
// mode 0: C = h, C2 = h*dis[m]^2 + bias
// mode 1: C = relu(h + bias)
// mode 2: C = h + bias
__global__ __launch_bounds__(256, 1)
void gemm_kernel(const float* __restrict__ A0, const float* __restrict__ A1,
                 const float* __restrict__ W, const float* __restrict__ bias,
                 float* __restrict__ C, float* __restrict__ C2,
                 int M, int mode)
{
    extern __shared__ float smem[];
    float* As = smem;               // [128][128] row-major
    float* Ws = smem + 128 * 128;   // [k][n] row-major

    const int tid = threadIdx.x;
    const int m0  = blockIdx.x * BM;

    const float4 z4 = make_float4(0.f, 0.f, 0.f, 0.f);
#pragma unroll
    for (int i = 0; i < 16; i++) {
        int f  = i * 256 + tid;       // float4 index
        int m  = f >> 5;
        int k4 = f & 31;
        int gm = m0 + m;
        float4 v = z4;
        if (gm < M) {
            const float* base = (gm < N_NODES) ? (A0 + (size_t)gm * D)
                                               : (A1 + (size_t)(gm - N_NODES) * D);
            v = __ldg((const float4*)base + k4);
        }
        *(float4*)(As + m * D + k4 * 4) = v;
    }
#pragma unroll
    for (int i = 0; i < 16; i++) {
        int f = i * 256 + tid;
        ((float4*)Ws)[f] = __ldg((const float4*)W + f);
    }
    __syncthreads();

    const int ty  = tid >> 4;     // 0..15
    const int tx  = tid & 15;     // 0..15
    const int row = ty * 8;
    const int col = tx * 8;

    unsigned long long acc[8][4];
#pragma unroll
    for (int i = 0; i < 8; i++)
#pragma unroll
        for (int j = 0; j < 4; j++) acc[i][j] = 0ull;

#pragma unroll 4
    for (int k = 0; k < D; k++) {
        ulonglong2 b01 = *(const ulonglong2*)(Ws + k * D + col);
        ulonglong2 b23 = *(const ulonglong2*)(Ws + k * D + col + 4);
        unsigned long long b[4] = {b01.x, b01.y, b23.x, b23.y};
#pragma unroll
        for (int i = 0; i < 8; i++) {
            unsigned long long aa;
            PACK_AA(aa, __float_as_uint(As[(row + i) * D + k]));
#pragma unroll
            for (int j = 0; j < 4; j++) FMA2(acc[i][j], aa, b[j], acc[i][j]);
        }
    }

    float bb[8];
    {
        float4 t0 = __ldg((const float4*)(bias + col));
        float4 t1 = __ldg((const float4*)(bias + col + 4));
        bb[0]=t0.x; bb[1]=t0.y; bb[2]=t0.z; bb[3]=t0.w;
        bb[4]=t1.x; bb[5]=t1.y; bb[6]=t1.z; bb[7]=t1.w;
    }
#pragma unroll
    for (int i = 0; i < 8; i++) {
        int m = m0 + row + i;
        if (m >= M) break;
        float v[8];
#pragma unroll
        for (int j = 0; j < 4; j++) UNPACK2(v[2*j], v[2*j+1], acc[i][j]);

        if (mode == 0) {
            float dd = g_dis[m];
            float d2 = dd * dd;
            float* cp  = C  + (size_t)m * D + col;
            float* cp2 = C2 + (size_t)m * D + col;
            *(float4*)cp       = make_float4(v[0], v[1], v[2], v[3]);
            *(float4*)(cp + 4) = make_float4(v[4], v[5], v[6], v[7]);
            *(float4*)cp2       = make_float4(fmaf(v[0], d2, bb[0]), fmaf(v[1], d2, bb[1]),
                                              fmaf(v[2], d2, bb[2]), fmaf(v[3], d2, bb[3]));
            *(float4*)(cp2 + 4) = make_float4(fmaf(v[4], d2, bb[4]), fmaf(v[5], d2, bb[5]),
                                              fmaf(v[6], d2, bb[6]), fmaf(v[7], d2, bb[7]));
        } else {
            float o[8];
#pragma unroll
            for (int j = 0; j < 8; j++) {
                float t = v[j] + bb[j];
                o[j] = (mode == 1) ? fmaxf(t, 0.0f) : t;
            }
            float* cp = C + (size_t)m * D + col;
            *(float4*)cp       = make_float4(o[0], o[1], o[2], o[3]);
            *(float4*)(cp + 4) = make_float4(o[4], o[5], o[6], o[7]);
        }
    }
}

// -------- gather: out[v] = relu( init[v] + sum_{e: dst=v} w_e * h[src_e] ) --------
// R4-proven shape: warp per node, unroll 2, dual accumulators
__global__ void gather_kernel(float* __restrict__ out) {
    int node = blockIdx.x * 8 + (threadIdx.x >> 5);
    int lane = threadIdx.x & 31;
    if (node >= NT) return;
    int beg = g_off[node];
    int cnt = g_cnt[node];
    float4 a0 = *((const float4*)(g_agg + (size_t)node * D) + lane);
    float4 a1 = make_float4(0.f, 0.f, 0.f, 0.f);

    int j = 0;
    for (; j + 2 <= cnt; j += 2) {
        int   s0 = __ldg(&g_csrc[beg + j]);
        int   s1 = __ldg(&g_csrc[beg + j + 1]);
        float w0 = __ldg(&g_cw[beg + j]);
        float w1 = __ldg(&g_cw[beg + j + 1]);
        float4 v0 = __ldg((const float4*)(g_h + (size_t)s0 * D) + lane);
        float4 v1 = __ldg((const float4*)(g_h + (size_t)s1 * D) + lane);
        a0.x = fmaf(w0, v0.x, a0.x); a0.y = fmaf(w0, v0.y, a0.y);
        a0.z = fmaf(w0, v0.z, a0.z); a0.w = fmaf(w0, v0.w, a0.w);
        a1.x = fmaf(w1, v1.x, a1.x); a1.y = fmaf(w1, v1.y, a1.y);
        a1.z = fmaf(w1, v1.z, a1.z); a1.w = fmaf(w1, v1.w, a1.w);
    }
    if (j < cnt) {
        int   s = __ldg(&g_csrc[beg + j]);
        float w = __ldg(&g_cw[beg + j]);
        float4 v = __ldg((const float4*)(g_h + (size_t)s * D) + lane);
        a0.x = fmaf(w, v.x, a0.x); a0.y = fmaf(w, v.y, a0.y);
        a0.z = fmaf(w, v.z, a0.z); a0.w = fmaf(w, v.w, a0.w);
    }
    a0.x = fmaxf(a0.x + a1.x, 0.0f);
    a0.y = fmaxf(a0.y + a1.y, 0.0f);
    a0.z = fmaxf(a0.z + a1.z, 0.0f);
    a0.w = fmaxf(a0.w + a1.w, 0.0f);
    *((float4*)(out + (size_t)node * D) + lane) = a0;
}

extern "C" void kernel_launch(void* const* d_in, const int* in_sizes, int n_in,
                              void* d_out, int out_size)
{
    const float* x    = (const float*)d_in[0];
    const int*   ei   = (const int*)  d_in[1];
    const float* xa   = (const float*)d_in[2];
    const int*   eia  = (const int*)  d_in[3];
    const float* W_in = (const float*)d_in[4];
    const float* b_in = (const float*)d_in[5];
    const float* W_h  = (const float*)d_in[6];
    const float* b_h  = (const float*)d_in[7];
    const float* W_out= (const float*)d_in[8];
    const float* b_out= (const float*)d_in[9];
    const float* Wf1  = (const float*)d_in[10];
    const float* bf1  = (const float*)d_in[11];
    const float* Wf2  = (const float*)d_in[12];
    const float* bf2  = (const float*)d_in[13];
    float* out = (float*)d_out;

    cudaFuncSetAttribute(gemm_kernel,
        cudaFuncAttributeMaxDynamicSharedMemorySize, GEMM_SMEM);

    float *hp, *aggp, *bufp;
    cudaGetSymbolAddress((void**)&hp,   g_h);
    cudaGetSymbolAddress((void**)&aggp, g_agg);
    cudaGetSymbolAddress((void**)&bufp, g_buf);

    const int gemm_blocks   = (NT + BM - 1) / BM;       // 782
    const int node_blocks   = (NT + 255) / 256;         // 391
    const int edge_blocks   = (NET + 255) / 256;        // 6250
    const int gather_blocks = (NT + 7) / 8;             // 12500

    // combined CSR build (once for both graphs)
    zero_kernel<<<node_blocks, 256>>>();
    count_kernel<<<edge_blocks, 256>>>(ei, eia);
    dis_kernel<<<node_blocks, 256>>>();
    scan1_kernel<<<SCAN_NBLK, 1024>>>();
    scan2_kernel<<<1, 128>>>();
    scan3_kernel<<<node_blocks, 256>>>();
    fill_kernel<<<edge_blocks, 256>>>(ei, eia);

    const float* Wl[3] = {W_in, W_h, W_out};
    const float* bl[3] = {b_in, b_h, b_out};

    // 3 GCN layers over the combined 100K-node batch
    const float* in0 = x;
    const float* in1 = xa;
    for (int l = 0; l < 3; l++) {
        gemm_kernel<<<gemm_blocks, 256, GEMM_SMEM>>>(
            in0, in1, Wl[l], bl[l], hp, aggp, NT, 0);
        gather_kernel<<<gather_blocks, 256>>>(bufp);
        in0 = bufp;
        in1 = bufp + (size_t)N_NODES * D;
    }

    // MLP head; final GEMM writes straight into d_out (out | out_aug layout)
    gemm_kernel<<<gemm_blocks, 256, GEMM_SMEM>>>(
        bufp, bufp + (size_t)N_NODES * D, Wf1, bf1, hp, nullptr, NT, 1);
    gemm_kernel<<<gemm_blocks, 256, GEMM_SMEM>>>(
        hp, hp + (size_t)N_NODES * D, Wf2, bf2, out, nullptr, NT, 2);
}

// round 7
// speedup vs baseline: 1.2921x; 1.0304x over previous
#include <cuda_runtime.h>
#include <cstdint>

#define N_NODES 50000
#define NT      100000          // combined node space (graph0 + graph1)
#define D 128
#define NE 800000
#define NET (2 * NE)
#define BM 128
#define SCAN_NBLK ((NT + 1023) / 1024)   // 98
#define GEMM_SMEM (2 * 128 * 128 * 4)    // As 64KB + Ws 64KB

// -------- device scratch --------
__device__ float g_h[(size_t)NT * D];     // h_scaled = (A@W) * dis[row]
__device__ float g_buf[(size_t)NT * D];
__device__ float g_dis[NT];
__device__ int   g_cnt[NT];
__device__ int   g_off[NT];
__device__ int   g_cur[NT];
__device__ int   g_csrc[NET];
__device__ int   g_bsum[128];

// packed f32x2 helpers (baseline sm_100+ PTX, not 'a'-gated)
#define PACK_AA(out, af) \
    asm("mov.b64 %0, {%1, %1};" : "=l"(out) : "r"(af))
#define FMA2(d, a, b, c) \
    asm("fma.rn.f32x2 %0, %1, %2, %3;" : "=l"(d) : "l"(a), "l"(b), "l"(c))
#define UNPACK2(lo, hi, in) \
    asm("mov.b64 {%0, %1}, %2;" : "=f"(lo), "=f"(hi) : "l"(in))

// -------- CSR build over combined edge set --------
__global__ void zero_kernel() {
    int i = blockIdx.x * blockDim.x + threadIdx.x;
    if (i < NT) { g_cnt[i] = 0; g_cur[i] = 0; }
}
__global__ void count_kernel(const int* __restrict__ e0, const int* __restrict__ e1) {
    int e = blockIdx.x * blockDim.x + threadIdx.x;
    if (e >= NET) return;
    int d = (e < NE) ? __ldg(e0 + NE + e) : (__ldg(e1 + NE + (e - NE)) + N_NODES);
    atomicAdd(&g_cnt[d], 1);
}
__global__ void dis_kernel() {
    int i = blockIdx.x * blockDim.x + threadIdx.x;
    if (i < NT) g_dis[i] = rsqrtf((float)g_cnt[i] + 1.0f);
}
__global__ void scan1_kernel() {
    __shared__ int sh[1024];
    int i = blockIdx.x * 1024 + threadIdx.x;
    int v = (i < NT) ? g_cnt[i] : 0;
    sh[threadIdx.x] = v;
    __syncthreads();
#pragma unroll
    for (int ofs = 1; ofs < 1024; ofs <<= 1) {
        int t = (threadIdx.x >= ofs) ? sh[threadIdx.x - ofs] : 0;
        __syncthreads();
        sh[threadIdx.x] += t;
        __syncthreads();
    }
    if (i < NT) g_off[i] = sh[threadIdx.x] - v;
    if (threadIdx.x == 1023) g_bsum[blockIdx.x] = sh[1023];
}
__global__ void scan2_kernel() {
    __shared__ int sh[128];
    int v = (threadIdx.x < SCAN_NBLK) ? g_bsum[threadIdx.x] : 0;
    sh[threadIdx.x] = v;
    __syncthreads();
#pragma unroll
    for (int ofs = 1; ofs < 128; ofs <<= 1) {
        int t = (threadIdx.x >= ofs) ? sh[threadIdx.x - ofs] : 0;
        __syncthreads();
        sh[threadIdx.x] += t;
        __syncthreads();
    }
    if (threadIdx.x < SCAN_NBLK) g_bsum[threadIdx.x] = sh[threadIdx.x] - v;
}
__global__ void scan3_kernel() {
    int i = blockIdx.x * blockDim.x + threadIdx.x;
    if (i < NT) g_off[i] += g_bsum[i >> 10];
}
__global__ void fill_kernel(const int* __restrict__ e0, const int* __restrict__ e1) {
    int e = blockIdx.x * blockDim.x + threadIdx.x;
    if (e >= NET) return;
    int s, d;
    if (e < NE) { s = __ldg(e0 + e);          d = __ldg(e0 + NE + e); }
    else        { s = __ldg(e1 + (e - NE)) + N_NODES;
                  d = __ldg(e1 + NE + (e - NE)) + N_NODES; }
    int p = g_off[d] + atomicAdd(&g_cur[d], 1);
    g_csrc[p] = s;
}

// -------- GEMM: C[M,128] = A[M,128] @ W[128,128] (+ epilogue), f32x2 --------
// Rows < N_NODES read from A0, rows >= N_NODES from A1 (row - N_NODES).
// mode 0: C = (A@W) * dis[m]       (pre-scaled h for GCN aggregation)
// mode 1: C = relu(A@W + bias)
// mode 2: C = A@W + bias
__global__ __launch_bounds__(256, 1)
void gemm_kernel(const float* __restrict__ A0, const float* __restrict__ A1,
                 const float* __restrict__ W, const float* __restrict__ bias,
                 float* __restrict__ C, int M, int mode)
{
    extern __shared__ float smem[];
    float* As = smem;               // [128][128] row-major
    float* Ws = smem + 128 * 128;   // [k][n] row-major

    const int tid = threadIdx.x;
    const int m0  = blockIdx.x * BM;

    const float4 z4 = make_float4(0.f, 0.f, 0.f, 0.f);
#pragma unroll
    for (int i = 0; i < 16; i++) {
        int f  = i * 256 + tid;       // float4 index
        int m  = f >> 5;
        int k4 = f & 31;
        int gm = m0 + m;
        float4 v = z4;
        if (gm < M) {
            const float* base = (gm < N_NODES) ? (A0 + (size_t)gm * D)
                                               : (A1 + (size_t)(gm - N_NODES) * D);
            v = __ldg((const float4*)base + k4);
        }
        *(float4*)(As + m * D + k4 * 4) = v;
    }
#pragma unroll
    for (int i = 0; i < 16; i++) {
        int f = i * 256 + tid;
        ((float4*)Ws)[f] = __ldg((const float4*)W + f);
    }
    __syncthreads();

    const int ty  = tid >> 4;     // 0..15
    const int tx  = tid & 15;     // 0..15
    const int row = ty * 8;
    const int col = tx * 8;

    unsigned long long acc[8][4];
#pragma unroll
    for (int i = 0; i < 8; i++)
#pragma unroll
        for (int j = 0; j < 4; j++) acc[i][j] = 0ull;

#pragma unroll 4
    for (int k = 0; k < D; k++) {
        ulonglong2 b01 = *(const ulonglong2*)(Ws + k * D + col);
        ulonglong2 b23 = *(const ulonglong2*)(Ws + k * D + col + 4);
        unsigned long long b[4] = {b01.x, b01.y, b23.x, b23.y};
#pragma unroll
        for (int i = 0; i < 8; i++) {
            unsigned long long aa;
            PACK_AA(aa, __float_as_uint(As[(row + i) * D + k]));
#pragma unroll
            for (int j = 0; j < 4; j++) FMA2(acc[i][j], aa, b[j], acc[i][j]);
        }
    }

    float bb[8] = {0, 0, 0, 0, 0, 0, 0, 0};
    if (mode != 0) {
        float4 t0 = __ldg((const float4*)(bias + col));
        float4 t1 = __ldg((const float4*)(bias + col + 4));
        bb[0]=t0.x; bb[1]=t0.y; bb[2]=t0.z; bb[3]=t0.w;
        bb[4]=t1.x; bb[5]=t1.y; bb[6]=t1.z; bb[7]=t1.w;
    }
#pragma unroll
    for (int i = 0; i < 8; i++) {
        int m = m0 + row + i;
        if (m >= M) break;
        float v[8];
#pragma unroll
        for (int j = 0; j < 4; j++) UNPACK2(v[2*j], v[2*j+1], acc[i][j]);

        float* cp = C + (size_t)m * D + col;
        if (mode == 0) {
            float dd = g_dis[m];
            *(float4*)cp       = make_float4(v[0]*dd, v[1]*dd, v[2]*dd, v[3]*dd);
            *(float4*)(cp + 4) = make_float4(v[4]*dd, v[5]*dd, v[6]*dd, v[7]*dd);
        } else {
            float o[8];
#pragma unroll
            for (int j = 0; j < 8; j++) {
                float t = v[j] + bb[j];
                o[j] = (mode == 1) ? fmaxf(t, 0.0f) : t;
            }
            *(float4*)cp       = make_float4(o[0], o[1], o[2], o[3]);
            *(float4*)(cp + 4) = make_float4(o[4], o[5], o[6], o[7]);
        }
    }
}

// -------- gather: out[v] = relu( bias + dis[v] * (hs[v] + sum_{e: dst=v} hs[src]) ) --------
// warp per node; launched per graph half (base offset) for L2 locality.
__global__ void gather_kernel(const float* __restrict__ bias,
                              float* __restrict__ out, int base) {
    int node = base + blockIdx.x * 8 + (threadIdx.x >> 5);
    int lane = threadIdx.x & 31;
    int beg = g_off[node];
    int cnt = g_cnt[node];

    // self contribution (hs[node]) starts a0; second accumulator for ILP
    float4 a0 = __ldg((const float4*)(g_h + (size_t)node * D) + lane);
    float4 a1 = make_float4(0.f, 0.f, 0.f, 0.f);

    int j = 0;
    for (; j + 2 <= cnt; j += 2) {
        int s0 = __ldg(&g_csrc[beg + j]);
        int s1 = __ldg(&g_csrc[beg + j + 1]);
        float4 v0 = __ldg((const float4*)(g_h + (size_t)s0 * D) + lane);
        float4 v1 = __ldg((const float4*)(g_h + (size_t)s1 * D) + lane);
        a0.x += v0.x; a0.y += v0.y; a0.z += v0.z; a0.w += v0.w;
        a1.x += v1.x; a1.y += v1.y; a1.z += v1.z; a1.w += v1.w;
    }
    if (j < cnt) {
        int s = __ldg(&g_csrc[beg + j]);
        float4 v = __ldg((const float4*)(g_h + (size_t)s * D) + lane);
        a0.x += v.x; a0.y += v.y; a0.z += v.z; a0.w += v.w;
    }
    float dd = __ldg(&g_dis[node]);
    float4 b4 = __ldg((const float4*)bias + lane);
    a0.x = fmaxf(fmaf(dd, a0.x + a1.x, b4.x), 0.0f);
    a0.y = fmaxf(fmaf(dd, a0.y + a1.y, b4.y), 0.0f);
    a0.z = fmaxf(fmaf(dd, a0.z + a1.z, b4.z), 0.0f);
    a0.w = fmaxf(fmaf(dd, a0.w + a1.w, b4.w), 0.0f);
    *((float4*)(out + (size_t)node * D) + lane) = a0;
}

extern "C" void kernel_launch(void* const* d_in, const int* in_sizes, int n_in,
                              void* d_out, int out_size)
{
    const float* x    = (const float*)d_in[0];
    const int*   ei   = (const int*)  d_in[1];
    const float* xa   = (const float*)d_in[2];
    const int*   eia  = (const int*)  d_in[3];
    const float* W_in = (const float*)d_in[4];
    const float* b_in = (const float*)d_in[5];
    const float* W_h  = (const float*)d_in[6];
    const float* b_h  = (const float*)d_in[7];
    const float* W_out= (const float*)d_in[8];
    const float* b_out= (const float*)d_in[9];
    const float* Wf1  = (const float*)d_in[10];
    const float* bf1  = (const float*)d_in[11];
    const float* Wf2  = (const float*)d_in[12];
    const float* bf2  = (const float*)d_in[13];
    float* out = (float*)d_out;

    cudaFuncSetAttribute(gemm_kernel,
        cudaFuncAttributeMaxDynamicSharedMemorySize, GEMM_SMEM);

    float *hp, *bufp;
    cudaGetSymbolAddress((void**)&hp,   g_h);
    cudaGetSymbolAddress((void**)&bufp, g_buf);

    const int gemm_blocks   = (NT + BM - 1) / BM;       // 782
    const int node_blocks   = (NT + 255) / 256;         // 391
    const int edge_blocks   = (NET + 255) / 256;        // 6250
    const int gather_blocks = N_NODES / 8;              // 6250 (per half)

    // combined CSR build (once for both graphs)
    zero_kernel<<<node_blocks, 256>>>();
    count_kernel<<<edge_blocks, 256>>>(ei, eia);
    dis_kernel<<<node_blocks, 256>>>();
    scan1_kernel<<<SCAN_NBLK, 1024>>>();
    scan2_kernel<<<1, 128>>>();
    scan3_kernel<<<node_blocks, 256>>>();
    fill_kernel<<<edge_blocks, 256>>>(ei, eia);

    const float* Wl[3] = {W_in, W_h, W_out};
    const float* bl[3] = {b_in, b_h, b_out};

    // 3 GCN layers: combined GEMM, per-half gathers (L2 locality)
    const float* in0 = x;
    const float* in1 = xa;
    for (int l = 0; l < 3; l++) {
        gemm_kernel<<<gemm_blocks, 256, GEMM_SMEM>>>(
            in0, in1, Wl[l], nullptr, hp, NT, 0);
        gather_kernel<<<gather_blocks, 256>>>(bl[l], bufp, 0);
        gather_kernel<<<gather_blocks, 256>>>(bl[l], bufp, N_NODES);
        in0 = bufp;
        in1 = bufp + (size_t)N_NODES * D;
    }

    // MLP head; final GEMM writes straight into d_out (out | out_aug layout)
    gemm_kernel<<<gemm_blocks, 256, GEMM_SMEM>>>(
        bufp, bufp + (size_t)N_NODES * D, Wf1, bf1, hp, NT, 1);
    gemm_kernel<<<gemm_blocks, 256, GEMM_SMEM>>>(
        hp, hp + (size_t)N_NODES * D, Wf2, bf2, out, NT, 2);
}

// round 8
// speedup vs baseline: 1.7090x; 1.3227x over previous
#include <cuda_runtime.h>
#include <cstdint>

#define N_NODES 50000
#define D 128
#define NE 800000
#define BM 128
#define SCAN_NBLK ((N_NODES + 1023) / 1024)   // 49
#define GEMM_SMEM (2 * 128 * 128 * 4)          // As 64KB + Ws 64KB

// -------- device scratch --------
__device__ float g_h[(size_t)N_NODES * D];    // hs = (A@W) * dis[row]
__device__ float g_buf[(size_t)N_NODES * D];
__device__ float g_dis[N_NODES];
__device__ int   g_cnt[N_NODES];
__device__ int   g_off[N_NODES];
__device__ int   g_cur[N_NODES];
__device__ int   g_csrc[NE];
__device__ int   g_bsum[64];

// packed f32x2 helpers (baseline sm_100+ PTX, not 'a'-gated)
#define PACK_AA(out, af) \
    asm("mov.b64 %0, {%1, %1};" : "=l"(out) : "r"(af))
#define FMA2(d, a, b, c) \
    asm("fma.rn.f32x2 %0, %1, %2, %3;" : "=l"(d) : "l"(a), "l"(b), "l"(c))
#define UNPACK2(lo, hi, in) \
    asm("mov.b64 {%0, %1}, %2;" : "=f"(lo), "=f"(hi) : "l"(in))

// -------- CSR build --------
__global__ void zero_kernel() {
    int i = blockIdx.x * blockDim.x + threadIdx.x;
    if (i < N_NODES) { g_cnt[i] = 0; g_cur[i] = 0; }
}
__global__ void count_kernel(const int* __restrict__ dst) {
    int e = blockIdx.x * blockDim.x + threadIdx.x;
    if (e < NE) atomicAdd(&g_cnt[dst[e]], 1);
}
__global__ void dis_kernel() {
    int i = blockIdx.x * blockDim.x + threadIdx.x;
    if (i < N_NODES) g_dis[i] = rsqrtf((float)g_cnt[i] + 1.0f);
}
__global__ void scan1_kernel() {
    __shared__ int sh[1024];
    int i = blockIdx.x * 1024 + threadIdx.x;
    int v = (i < N_NODES) ? g_cnt[i] : 0;
    sh[threadIdx.x] = v;
    __syncthreads();
#pragma unroll
    for (int ofs = 1; ofs < 1024; ofs <<= 1) {
        int t = (threadIdx.x >= ofs) ? sh[threadIdx.x - ofs] : 0;
        __syncthreads();
        sh[threadIdx.x] += t;
        __syncthreads();
    }
    if (i < N_NODES) g_off[i] = sh[threadIdx.x] - v;
    if (threadIdx.x == 1023) g_bsum[blockIdx.x] = sh[1023];
}
__global__ void scan2_kernel() {
    __shared__ int sh[64];
    int v = (threadIdx.x < SCAN_NBLK) ? g_bsum[threadIdx.x] : 0;
    sh[threadIdx.x] = v;
    __syncthreads();
#pragma unroll
    for (int ofs = 1; ofs < 64; ofs <<= 1) {
        int t = (threadIdx.x >= ofs) ? sh[threadIdx.x - ofs] : 0;
        __syncthreads();
        sh[threadIdx.x] += t;
        __syncthreads();
    }
    if (threadIdx.x < SCAN_NBLK) g_bsum[threadIdx.x] = sh[threadIdx.x] - v;
}
__global__ void scan3_kernel() {
    int i = blockIdx.x * blockDim.x + threadIdx.x;
    if (i < N_NODES) g_off[i] += g_bsum[i >> 10];
}
__global__ void fill_kernel(const int* __restrict__ src, const int* __restrict__ dst) {
    int e = blockIdx.x * blockDim.x + threadIdx.x;
    if (e >= NE) return;
    int s = src[e], d = dst[e];
    int p = g_off[d] + atomicAdd(&g_cur[d], 1);
    g_csrc[p] = s;
}

// -------- GEMM: C[M,128] = A[M,128] @ W[128,128] (+ epilogue), f32x2 --------
// mode 0: C = (A@W) * dis[m]       (pre-scaled hs)
// mode 1: C = relu(A@W + bias)
// mode 2: C = A@W + bias
__global__ __launch_bounds__(256, 1)
void gemm_kernel(const float* __restrict__ A, const float* __restrict__ W,
                 const float* __restrict__ bias,
                 float* __restrict__ C, int M, int mode)
{
    extern __shared__ float smem[];
    float* As = smem;               // [128][128] row-major
    float* Ws = smem + 128 * 128;   // [k][n] row-major

    const int tid = threadIdx.x;
    const int m0  = blockIdx.x * BM;

    const float4 z4 = make_float4(0.f, 0.f, 0.f, 0.f);
#pragma unroll
    for (int i = 0; i < 16; i++) {
        int f  = i * 256 + tid;       // float4 index
        int m  = f >> 5;
        int k4 = f & 31;
        float4 v = (m0 + m < M)
            ? __ldg((const float4*)(A + (size_t)(m0 + m) * D) + k4) : z4;
        *(float4*)(As + m * D + k4 * 4) = v;
    }
#pragma unroll
    for (int i = 0; i < 16; i++) {
        int f = i * 256 + tid;
        ((float4*)Ws)[f] = __ldg((const float4*)W + f);
    }
    __syncthreads();

    const int ty  = tid >> 4;     // 0..15
    const int tx  = tid & 15;     // 0..15
    const int row = ty * 8;
    const int col = tx * 8;

    unsigned long long acc[8][4];
#pragma unroll
    for (int i = 0; i < 8; i++)
#pragma unroll
        for (int j = 0; j < 4; j++) acc[i][j] = 0ull;

#pragma unroll 4
    for (int k = 0; k < D; k++) {
        ulonglong2 b01 = *(const ulonglong2*)(Ws + k * D + col);
        ulonglong2 b23 = *(const ulonglong2*)(Ws + k * D + col + 4);
        unsigned long long b[4] = {b01.x, b01.y, b23.x, b23.y};
#pragma unroll
        for (int i = 0; i < 8; i++) {
            unsigned long long aa;
            PACK_AA(aa, __float_as_uint(As[(row + i) * D + k]));
#pragma unroll
            for (int j = 0; j < 4; j++) FMA2(acc[i][j], aa, b[j], acc[i][j]);
        }
    }

    float bb[8] = {0, 0, 0, 0, 0, 0, 0, 0};
    if (mode != 0) {
        float4 t0 = __ldg((const float4*)(bias + col));
        float4 t1 = __ldg((const float4*)(bias + col + 4));
        bb[0]=t0.x; bb[1]=t0.y; bb[2]=t0.z; bb[3]=t0.w;
        bb[4]=t1.x; bb[5]=t1.y; bb[6]=t1.z; bb[7]=t1.w;
    }
#pragma unroll
    for (int i = 0; i < 8; i++) {
        int m = m0 + row + i;
        if (m >= M) break;
        float v[8];
#pragma unroll
        for (int j = 0; j < 4; j++) UNPACK2(v[2*j], v[2*j+1], acc[i][j]);

        float* cp = C + (size_t)m * D + col;
        if (mode == 0) {
            float dd = g_dis[m];
            *(float4*)cp       = make_float4(v[0]*dd, v[1]*dd, v[2]*dd, v[3]*dd);
            *(float4*)(cp + 4) = make_float4(v[4]*dd, v[5]*dd, v[6]*dd, v[7]*dd);
        } else {
            float o[8];
#pragma unroll
            for (int j = 0; j < 8; j++) {
                float t = v[j] + bb[j];
                o[j] = (mode == 1) ? fmaxf(t, 0.0f) : t;
            }
            *(float4*)cp       = make_float4(o[0], o[1], o[2], o[3]);
            *(float4*)(cp + 4) = make_float4(o[4], o[5], o[6], o[7]);
        }
    }
}

// -------- gather: out[v] = relu( bias + dis[v] * (hs[v] + sum_{e: dst=v} hs[src]) ) --------
__global__ void gather_kernel(const float* __restrict__ bias, float* __restrict__ out) {
    int node = blockIdx.x * 8 + (threadIdx.x >> 5);
    int lane = threadIdx.x & 31;
    if (node >= N_NODES) return;
    int beg = g_off[node];
    int cnt = g_cnt[node];

    float4 a0 = __ldg((const float4*)(g_h + (size_t)node * D) + lane);  // self
    float4 a1 = make_float4(0.f, 0.f, 0.f, 0.f);

    int j = 0;
    for (; j + 2 <= cnt; j += 2) {
        int s0 = __ldg(&g_csrc[beg + j]);
        int s1 = __ldg(&g_csrc[beg + j + 1]);
        float4 v0 = __ldg((const float4*)(g_h + (size_t)s0 * D) + lane);
        float4 v1 = __ldg((const float4*)(g_h + (size_t)s1 * D) + lane);
        a0.x += v0.x; a0.y += v0.y; a0.z += v0.z; a0.w += v0.w;
        a1.x += v1.x; a1.y += v1.y; a1.z += v1.z; a1.w += v1.w;
    }
    if (j < cnt) {
        int s = __ldg(&g_csrc[beg + j]);
        float4 v = __ldg((const float4*)(g_h + (size_t)s * D) + lane);
        a0.x += v.x; a0.y += v.y; a0.z += v.z; a0.w += v.w;
    }
    float dd = __ldg(&g_dis[node]);
    float4 b4 = __ldg((const float4*)bias + lane);
    a0.x = fmaxf(fmaf(dd, a0.x + a1.x, b4.x), 0.0f);
    a0.y = fmaxf(fmaf(dd, a0.y + a1.y, b4.y), 0.0f);
    a0.z = fmaxf(fmaf(dd, a0.z + a1.z, b4.z), 0.0f);
    a0.w = fmaxf(fmaf(dd, a0.w + a1.w, b4.w), 0.0f);
    *((float4*)(out + (size_t)node * D) + lane) = a0;
}

extern "C" void kernel_launch(void* const* d_in, const int* in_sizes, int n_in,
                              void* d_out, int out_size)
{
    const float* x    = (const float*)d_in[0];
    const int*   ei   = (const int*)  d_in[1];
    const float* xa   = (const float*)d_in[2];
    const int*   eia  = (const int*)  d_in[3];
    const float* W_in = (const float*)d_in[4];
    const float* b_in = (const float*)d_in[5];
    const float* W_h  = (const float*)d_in[6];
    const float* b_h  = (const float*)d_in[7];
    const float* W_out= (const float*)d_in[8];
    const float* b_out= (const float*)d_in[9];
    const float* Wf1  = (const float*)d_in[10];
    const float* bf1  = (const float*)d_in[11];
    const float* Wf2  = (const float*)d_in[12];
    const float* bf2  = (const float*)d_in[13];
    float* out = (float*)d_out;

    cudaFuncSetAttribute(gemm_kernel,
        cudaFuncAttributeMaxDynamicSharedMemorySize, GEMM_SMEM);

    float *hp, *bufp;
    cudaGetSymbolAddress((void**)&hp,   g_h);
    cudaGetSymbolAddress((void**)&bufp, g_buf);

    const int gemm_blocks   = (N_NODES + BM - 1) / BM;   // 391
    const int node_blocks   = (N_NODES + 255) / 256;
    const int edge_blocks   = (NE + 255) / 256;
    const int gather_blocks = (N_NODES + 7) / 8;

    const float* Wl[3] = {W_in, W_h, W_out};
    const float* bl[3] = {b_in, b_h, b_out};

    for (int g = 0; g < 2; g++) {
        const float* X   = g ? xa : x;
        const int*   src = (g ? eia : ei);
        const int*   dst = src + NE;
        float* OUT = out + (size_t)g * N_NODES * D;

        zero_kernel<<<node_blocks, 256>>>();
        count_kernel<<<edge_blocks, 256>>>(dst);
        dis_kernel<<<node_blocks, 256>>>();
        scan1_kernel<<<SCAN_NBLK, 1024>>>();
        scan2_kernel<<<1, 64>>>();
        scan3_kernel<<<node_blocks, 256>>>();
        fill_kernel<<<edge_blocks, 256>>>(src, dst);

        const float* in = X;
        for (int l = 0; l < 3; l++) {
            gemm_kernel<<<gemm_blocks, 256, GEMM_SMEM>>>(
                in, Wl[l], nullptr, hp, N_NODES, 0);
            gather_kernel<<<gather_blocks, 256>>>(bl[l], bufp);
            in = bufp;
        }

        gemm_kernel<<<gemm_blocks, 256, GEMM_SMEM>>>(
            bufp, Wf1, bf1, hp, N_NODES, 1);
        gemm_kernel<<<gemm_blocks, 256, GEMM_SMEM>>>(
            hp, Wf2, bf2, OUT, N_NODES, 2);
    }
}

// round 10
// speedup vs baseline: 1.8027x; 1.0548x over previous
#include <cuda_runtime.h>
#include <cuda_fp16.h>
#include <cstdint>

#define N_NODES 50000
#define D 128
#define NE 800000
#define BM 128
#define SCAN_NBLK ((N_NODES + 1023) / 1024)   // 49
#define GEMM_SMEM (2 * 128 * 128 * 4)          // As 64KB + Ws 64KB

// -------- device scratch --------
__device__ __half g_h[(size_t)N_NODES * D];   // hs = (A@W)*dis[row], fp16
__device__ float  g_buf[(size_t)N_NODES * D];
__device__ float  g_mlp[(size_t)N_NODES * D]; // MLP hidden scratch
__device__ float  g_dis[N_NODES];
__device__ int    g_cnt[N_NODES];
__device__ int    g_off[N_NODES];
__device__ int    g_cur[N_NODES];
__device__ int    g_csrc[NE];
__device__ int    g_bsum[64];

// packed f32x2 helpers (baseline sm_100+ PTX, not 'a'-gated)
#define PACK_AA(out, af) \
    asm("mov.b64 %0, {%1, %1};" : "=l"(out) : "r"(af))
#define FMA2(d, a, b, c) \
    asm("fma.rn.f32x2 %0, %1, %2, %3;" : "=l"(d) : "l"(a), "l"(b), "l"(c))
#define UNPACK2(lo, hi, in) \
    asm("mov.b64 {%0, %1}, %2;" : "=f"(lo), "=f"(hi) : "l"(in))

// -------- CSR build --------
__global__ void zero_kernel() {
    int i = blockIdx.x * blockDim.x + threadIdx.x;
    if (i < N_NODES) { g_cnt[i] = 0; g_cur[i] = 0; }
}
__global__ void count_kernel(const int* __restrict__ dst) {
    int e = blockIdx.x * blockDim.x + threadIdx.x;
    if (e < NE) atomicAdd(&g_cnt[dst[e]], 1);
}
__global__ void dis_kernel() {
    int i = blockIdx.x * blockDim.x + threadIdx.x;
    if (i < N_NODES) g_dis[i] = rsqrtf((float)g_cnt[i] + 1.0f);
}
__global__ void scan1_kernel() {
    __shared__ int sh[1024];
    int i = blockIdx.x * 1024 + threadIdx.x;
    int v = (i < N_NODES) ? g_cnt[i] : 0;
    sh[threadIdx.x] = v;
    __syncthreads();
#pragma unroll
    for (int ofs = 1; ofs < 1024; ofs <<= 1) {
        int t = (threadIdx.x >= ofs) ? sh[threadIdx.x - ofs] : 0;
        __syncthreads();
        sh[threadIdx.x] += t;
        __syncthreads();
    }
    if (i < N_NODES) g_off[i] = sh[threadIdx.x] - v;
    if (threadIdx.x == 1023) g_bsum[blockIdx.x] = sh[1023];
}
__global__ void scan2_kernel() {
    __shared__ int sh[64];
    int v = (threadIdx.x < SCAN_NBLK) ? g_bsum[threadIdx.x] : 0;
    sh[threadIdx.x] = v;
    __syncthreads();
#pragma unroll
    for (int ofs = 1; ofs < 64; ofs <<= 1) {
        int t = (threadIdx.x >= ofs) ? sh[threadIdx.x - ofs] : 0;
        __syncthreads();
        sh[threadIdx.x] += t;
        __syncthreads();
    }
    if (threadIdx.x < SCAN_NBLK) g_bsum[threadIdx.x] = sh[threadIdx.x] - v;
}
__global__ void scan3_kernel() {
    int i = blockIdx.x * blockDim.x + threadIdx.x;
    if (i < N_NODES) g_off[i] += g_bsum[i >> 10];
}
__global__ void fill_kernel(const int* __restrict__ src, const int* __restrict__ dst) {
    int e = blockIdx.x * blockDim.x + threadIdx.x;
    if (e >= NE) return;
    int s = src[e], d = dst[e];
    int p = g_off[d] + atomicAdd(&g_cur[d], 1);
    g_csrc[p] = s;
}

// -------- GEMM: C[M,128] = A[M,128] @ W[128,128] (+ epilogue), f32x2 --------
// mode 0: Ch = half( (A@W) * dis[m] )   (pre-scaled hs, fp16)
// mode 1: C = relu(A@W + bias)
// mode 2: C = A@W + bias
__global__ __launch_bounds__(256, 1)
void gemm_kernel(const float* __restrict__ A, const float* __restrict__ W,
                 const float* __restrict__ bias,
                 float* __restrict__ C, __half* __restrict__ Ch,
                 int M, int mode)
{
    extern __shared__ float smem[];
    float* As = smem;               // [128][128] row-major
    float* Ws = smem + 128 * 128;   // [k][n] row-major

    const int tid = threadIdx.x;
    const int m0  = blockIdx.x * BM;

    const float4 z4 = make_float4(0.f, 0.f, 0.f, 0.f);
#pragma unroll
    for (int i = 0; i < 16; i++) {
        int f  = i * 256 + tid;       // float4 index
        int m  = f >> 5;
        int k4 = f & 31;
        float4 v = (m0 + m < M)
            ? __ldg((const float4*)(A + (size_t)(m0 + m) * D) + k4) : z4;
        *(float4*)(As + m * D + k4 * 4) = v;
    }
#pragma unroll
    for (int i = 0; i < 16; i++) {
        int f = i * 256 + tid;
        ((float4*)Ws)[f] = __ldg((const float4*)W + f);
    }
    __syncthreads();

    const int ty  = tid >> 4;     // 0..15
    const int tx  = tid & 15;     // 0..15
    const int row = ty * 8;
    const int col = tx * 8;

    unsigned long long acc[8][4];
#pragma unroll
    for (int i = 0; i < 8; i++)
#pragma unroll
        for (int j = 0; j < 4; j++) acc[i][j] = 0ull;

#pragma unroll 4
    for (int k = 0; k < D; k++) {
        ulonglong2 b01 = *(const ulonglong2*)(Ws + k * D + col);
        ulonglong2 b23 = *(const ulonglong2*)(Ws + k * D + col + 4);
        unsigned long long b[4] = {b01.x, b01.y, b23.x, b23.y};
#pragma unroll
        for (int i = 0; i < 8; i++) {
            unsigned long long aa;
            PACK_AA(aa, __float_as_uint(As[(row + i) * D + k]));
#pragma unroll
            for (int j = 0; j < 4; j++) FMA2(acc[i][j], aa, b[j], acc[i][j]);
        }
    }

    float bb[8] = {0, 0, 0, 0, 0, 0, 0, 0};
    if (mode != 0) {
        float4 t0 = __ldg((const float4*)(bias + col));
        float4 t1 = __ldg((const float4*)(bias + col + 4));
        bb[0]=t0.x; bb[1]=t0.y; bb[2]=t0.z; bb[3]=t0.w;
        bb[4]=t1.x; bb[5]=t1.y; bb[6]=t1.z; bb[7]=t1.w;
    }
#pragma unroll
    for (int i = 0; i < 8; i++) {
        int m = m0 + row + i;
        if (m >= M) break;
        float v[8];
#pragma unroll
        for (int j = 0; j < 4; j++) UNPACK2(v[2*j], v[2*j+1], acc[i][j]);

        if (mode == 0) {
            float dd = g_dis[m];
            __half2 h0 = __floats2half2_rn(v[0]*dd, v[1]*dd);
            __half2 h1 = __floats2half2_rn(v[2]*dd, v[3]*dd);
            __half2 h2 = __floats2half2_rn(v[4]*dd, v[5]*dd);
            __half2 h3 = __floats2half2_rn(v[6]*dd, v[7]*dd);
            uint4 pk;
            pk.x = *(uint32_t*)&h0; pk.y = *(uint32_t*)&h1;
            pk.z = *(uint32_t*)&h2; pk.w = *(uint32_t*)&h3;
            *(uint4*)(Ch + (size_t)m * D + col) = pk;
        } else {
            float o[8];
#pragma unroll
            for (int j = 0; j < 8; j++) {
                float t = v[j] + bb[j];
                o[j] = (mode == 1) ? fmaxf(t, 0.0f) : t;
            }
            float* cp = C + (size_t)m * D + col;
            *(float4*)cp       = make_float4(o[0], o[1], o[2], o[3]);
            *(float4*)(cp + 4) = make_float4(o[4], o[5], o[6], o[7]);
        }
    }
}

// -------- gather: out[v] = relu( bias + dis[v] * (hs[v] + sum_{e: dst=v} hs[src]) ) --------
// warp per node; lane owns 4 halves (uint2 load) -> fp32 accum -> float4 store
__global__ void gather_kernel(const float* __restrict__ bias, float* __restrict__ out) {
    int node = blockIdx.x * 8 + (threadIdx.x >> 5);
    int lane = threadIdx.x & 31;
    if (node >= N_NODES) return;
    int beg = g_off[node];
    int cnt = g_cnt[node];

    float4 a0, a1 = make_float4(0.f, 0.f, 0.f, 0.f);
    {
        uint2 raw = __ldg((const uint2*)(g_h + (size_t)node * D) + lane);
        float2 f0 = __half22float2(*(__half2*)&raw.x);
        float2 f1 = __half22float2(*(__half2*)&raw.y);
        a0 = make_float4(f0.x, f0.y, f1.x, f1.y);
    }

    int j = 0;
    for (; j + 2 <= cnt; j += 2) {
        int s0 = __ldg(&g_csrc[beg + j]);
        int s1 = __ldg(&g_csrc[beg + j + 1]);
        uint2 r0 = __ldg((const uint2*)(g_h + (size_t)s0 * D) + lane);
        uint2 r1 = __ldg((const uint2*)(g_h + (size_t)s1 * D) + lane);
        float2 p0 = __half22float2(*(__half2*)&r0.x);
        float2 p1 = __half22float2(*(__half2*)&r0.y);
        float2 q0 = __half22float2(*(__half2*)&r1.x);
        float2 q1 = __half22float2(*(__half2*)&r1.y);
        a0.x += p0.x; a0.y += p0.y; a0.z += p1.x; a0.w += p1.y;
        a1.x += q0.x; a1.y += q0.y; a1.z += q1.x; a1.w += q1.y;
    }
    if (j < cnt) {
        int s = __ldg(&g_csrc[beg + j]);
        uint2 r = __ldg((const uint2*)(g_h + (size_t)s * D) + lane);
        float2 p0 = __half22float2(*(__half2*)&r.x);
        float2 p1 = __half22float2(*(__half2*)&r.y);
        a0.x += p0.x; a0.y += p0.y; a0.z += p1.x; a0.w += p1.y;
    }
    float dd = __ldg(&g_dis[node]);
    float4 b4 = __ldg((const float4*)bias + lane);
    a0.x = fmaxf(fmaf(dd, a0.x + a1.x, b4.x), 0.0f);
    a0.y = fmaxf(fmaf(dd, a0.y + a1.y, b4.y), 0.0f);
    a0.z = fmaxf(fmaf(dd, a0.z + a1.z, b4.z), 0.0f);
    a0.w = fmaxf(fmaf(dd, a0.w + a1.w, b4.w), 0.0f);
    *((float4*)(out + (size_t)node * D) + lane) = a0;
}

extern "C" void kernel_launch(void* const* d_in, const int* in_sizes, int n_in,
                              void* d_out, int out_size)
{
    const float* x    = (const float*)d_in[0];
    const int*   ei   = (const int*)  d_in[1];
    const float* xa   = (const float*)d_in[2];
    const int*   eia  = (const int*)  d_in[3];
    const float* W_in = (const float*)d_in[4];
    const float* b_in = (const float*)d_in[5];
    const float* W_h  = (const float*)d_in[6];
    const float* b_h  = (const float*)d_in[7];
    const float* W_out= (const float*)d_in[8];
    const float* b_out= (const float*)d_in[9];
    const float* Wf1  = (const float*)d_in[10];
    const float* bf1  = (const float*)d_in[11];
    const float* Wf2  = (const float*)d_in[12];
    const float* bf2  = (const float*)d_in[13];
    float* out = (float*)d_out;

    cudaFuncSetAttribute(gemm_kernel,
        cudaFuncAttributeMaxDynamicSharedMemorySize, GEMM_SMEM);

    __half* hp;
    float *bufp, *mlpp;
    cudaGetSymbolAddress((void**)&hp,   g_h);
    cudaGetSymbolAddress((void**)&bufp, g_buf);
    cudaGetSymbolAddress((void**)&mlpp, g_mlp);

    const int gemm_blocks   = (N_NODES + BM - 1) / BM;   // 391
    const int node_blocks   = (N_NODES + 255) / 256;
    const int edge_blocks   = (NE + 255) / 256;
    const int gather_blocks = (N_NODES + 7) / 8;

    const float* Wl[3] = {W_in, W_h, W_out};
    const float* bl[3] = {b_in, b_h, b_out};

    for (int g = 0; g < 2; g++) {
        const float* X   = g ? xa : x;
        const int*   src = (g ? eia : ei);
        const int*   dst = src + NE;
        float* OUT = out + (size_t)g * N_NODES * D;

        zero_kernel<<<node_blocks, 256>>>();
        count_kernel<<<edge_blocks, 256>>>(dst);
        dis_kernel<<<node_blocks, 256>>>();
        scan1_kernel<<<SCAN_NBLK, 1024>>>();
        scan2_kernel<<<1, 64>>>();
        scan3_kernel<<<node_blocks, 256>>>();
        fill_kernel<<<edge_blocks, 256>>>(src, dst);

        const float* in = X;
        for (int l = 0; l < 3; l++) {
            gemm_kernel<<<gemm_blocks, 256, GEMM_SMEM>>>(
                in, Wl[l], nullptr, nullptr, hp, N_NODES, 0);
            gather_kernel<<<gather_blocks, 256>>>(bl[l], bufp);
            in = bufp;
        }

        // MLP head: buf -> mlp (relu) -> OUT
        gemm_kernel<<<gemm_blocks, 256, GEMM_SMEM>>>(
            bufp, Wf1, bf1, mlpp, nullptr, N_NODES, 1);
        gemm_kernel<<<gemm_blocks, 256, GEMM_SMEM>>>(
            mlpp, Wf2, bf2, OUT, nullptr, N_NODES, 2);
    }
}